// round 2
// baseline (speedup 1.0000x reference)
#include <cuda_runtime.h>
#include <cuda_bf16.h>
#include <cstdint>

// DIN sequence encoder, B=4096, L=200, E=A=128.
// Factorization: att_in@W1 = q@(W1a+W1c) + keys_p@[(W1b-W1c) + diag(q)*W1d]
// One CTA per batch row. fp32 with packed fma.rn.f32x2 (sm_103a).

#define EB 128      // E
#define AB 128      // A
#define LK 200      // L
#define TLR 64      // l-tile rows for main tiles (3 tiles = 192), tail = 8

__device__ float g_W1q[EB * AB];   // W1a + W1c
__device__ float g_W1k[EB * AB];   // W1b - W1c
__device__ int   g_len64;          // 1 if keys_length is int64, 0 if int32

__global__ void prep_kernel(const float* __restrict__ W1) {
    int i = blockIdx.x * blockDim.x + threadIdx.x;
    if (i < EB * AB) {
        float c = W1[2 * EB * AB + i];
        g_W1q[i] = W1[i] + c;
        g_W1k[i] = W1[EB * AB + i] - c;
    }
}

// Single-block dtype sniffer for keys_length (B int32 words vs B int64 words).
// If int64 with values in [1,200], every odd 32-bit word of the first B words
// is zero. If int32, odd words hold random lengths in [1,200] (never 0).
__global__ void detect_len_kernel(const unsigned int* __restrict__ kl_words, int B) {
    __shared__ int any_nonzero_odd;
    if (threadIdx.x == 0) any_nonzero_odd = 0;
    __syncthreads();
    int local = 0;
    for (int i = threadIdx.x; i < B / 2; i += blockDim.x)
        if (kl_words[2 * i + 1] != 0u) local = 1;
    if (__syncthreads_or(local)) {
        if (threadIdx.x == 0) g_len64 = 0;
    } else {
        if (threadIdx.x == 0) g_len64 = 1;
    }
}

__device__ __forceinline__ unsigned long long packdup(float x) {
    unsigned long long r;
    asm("mov.b64 %0, {%1,%1};" : "=l"(r) : "f"(x));
    return r;
}
__device__ __forceinline__ void unpack2(unsigned long long v, float& lo, float& hi) {
    asm("mov.b64 {%0,%1}, %2;" : "=f"(lo), "=f"(hi) : "l"(v));
}
__device__ __forceinline__ void fma2(unsigned long long& d, unsigned long long a, unsigned long long b) {
    asm("fma.rn.f32x2 %0, %1, %2, %0;" : "+l"(d) : "l"(a), "l"(b));
}

// SMEM layout (floats)
#define OFF_WB   0                       // 128*128
#define OFF_W2   (OFF_WB + 16384)        // 128*128
#define OFF_KT   (OFF_W2 + 16384)        // 128*64  (transposed keys_p tile: [e][l])
#define OFF_H1   (OFF_KT + 8192)         // 128*68  (transposed H1 tile: [j][l], padded)
#define OFF_Q    (OFF_H1 + 8704)         // 128
#define OFF_U    (OFF_Q + 128)           // 128
#define OFF_B2   (OFF_U + 128)           // 128
#define OFF_W3   (OFF_B2 + 128)          // 128
#define OFF_SC   (OFF_W3 + 128)          // 208
#define OFF_RED  (OFF_SC + 208)          // 256
#define SMEM_FLOATS (OFF_RED + 256)
#define SMEM_BYTES  (SMEM_FLOATS * 4)

__global__ void __launch_bounds__(256, 1) din_kernel(
    const float* __restrict__ query,
    const float* __restrict__ keys,
    const void*  __restrict__ keys_length,
    const float* __restrict__ pos_emb,
    const float* __restrict__ W1,
    const float* __restrict__ b1,
    const float* __restrict__ W2,
    const float* __restrict__ b2,
    const float* __restrict__ W3,
    const float* __restrict__ b3,
    float* __restrict__ out)
{
    extern __shared__ float sm[];
    float* sWb  = sm + OFF_WB;
    float* sW2  = sm + OFF_W2;
    float* sKt  = sm + OFF_KT;
    float* sH1t = sm + OFF_H1;
    float* sQ   = sm + OFF_Q;
    float* sU   = sm + OFF_U;
    float* sB2  = sm + OFF_B2;
    float* sW3  = sm + OFF_W3;
    float* sSc  = sm + OFF_SC;
    float* sRed = sm + OFF_RED;

    const int b = blockIdx.x;
    const int t = threadIdx.x;

    // ---- setup ----
    if (t < 128) sQ[t] = query[(size_t)b * EB + t];
    __syncthreads();

    // Wb = W1k + diag(q) * W1d ; also stage W2
    #pragma unroll 4
    for (int i = t; i < EB * AB; i += 256) {
        int e = i >> 7;
        sWb[i] = g_W1k[i] + sQ[e] * W1[3 * EB * AB + i];
        sW2[i] = W2[i];
    }
    if (t < 128) {
        float acc = b1[t];
        #pragma unroll 8
        for (int e = 0; e < EB; e++) acc += sQ[e] * g_W1q[e * AB + t];
        sU[t]  = acc;
        sB2[t] = b2[t];
        sW3[t] = W3[t];
    }
    if (t < 208) sSc[t] = (t < LK) ? b3[0] : 0.0f;
    __syncthreads();

    // thread tiling: lt selects 4 l-rows, at selects cols {4at..4at+3, 64+4at..64+4at+3}
    const int lt = t >> 4;          // 0..15
    const int at = t & 15;          // 0..15
    const int lb = lt * 4;
    const int c0 = 4 * at;          // first col group base
    const int c1 = 64 + 4 * at;     // second col group base

    // ---- main tiles: l0 = 0, 64, 128 ----
    for (int l0 = 0; l0 < 192; l0 += TLR) {
        // load keys_p tile transposed: sKt[e*64 + l]
        #pragma unroll 4
        for (int idx = t; idx < TLR * EB; idx += 256) {
            int l = idx >> 7, e = idx & 127;
            sKt[e * 64 + l] = keys[((size_t)b * LK + l0 + l) * EB + e]
                            + pos_emb[(l0 + l) * EB + e];
        }
        __syncthreads();

        // GEMM1: z1[l, a] = keys_p @ Wb
        unsigned long long acc[4][4];
        #pragma unroll
        for (int j = 0; j < 4; j++)
            #pragma unroll
            for (int k = 0; k < 4; k++) acc[j][k] = 0ULL;

        #pragma unroll 4
        for (int e = 0; e < EB; e++) {
            float4 k4 = *(const float4*)(sKt + e * 64 + lb);
            ulonglong2 b0 = *(const ulonglong2*)(sWb + e * AB + c0);
            ulonglong2 b1v = *(const ulonglong2*)(sWb + e * AB + c1);
            unsigned long long a0 = packdup(k4.x), a1 = packdup(k4.y);
            unsigned long long a2 = packdup(k4.z), a3 = packdup(k4.w);
            fma2(acc[0][0], a0, b0.x); fma2(acc[0][1], a0, b0.y);
            fma2(acc[0][2], a0, b1v.x); fma2(acc[0][3], a0, b1v.y);
            fma2(acc[1][0], a1, b0.x); fma2(acc[1][1], a1, b0.y);
            fma2(acc[1][2], a1, b1v.x); fma2(acc[1][3], a1, b1v.y);
            fma2(acc[2][0], a2, b0.x); fma2(acc[2][1], a2, b0.y);
            fma2(acc[2][2], a2, b1v.x); fma2(acc[2][3], a2, b1v.y);
            fma2(acc[3][0], a3, b0.x); fma2(acc[3][1], a3, b0.y);
            fma2(acc[3][2], a3, b1v.x); fma2(acc[3][3], a3, b1v.y);
        }

        // epilogue: relu(z1 + u), write transposed into sH1t[j][l]
        {
            float hv[4][8];
            #pragma unroll
            for (int j = 0; j < 4; j++) {
                unpack2(acc[j][0], hv[j][0], hv[j][1]);
                unpack2(acc[j][1], hv[j][2], hv[j][3]);
                unpack2(acc[j][2], hv[j][4], hv[j][5]);
                unpack2(acc[j][3], hv[j][6], hv[j][7]);
            }
            #pragma unroll
            for (int k = 0; k < 8; k++) {
                int col = (k < 4) ? (c0 + k) : (c1 + k - 4);
                float u = sU[col];
                float4 st;
                st.x = fmaxf(hv[0][k] + u, 0.0f);
                st.y = fmaxf(hv[1][k] + u, 0.0f);
                st.z = fmaxf(hv[2][k] + u, 0.0f);
                st.w = fmaxf(hv[3][k] + u, 0.0f);
                *(float4*)(sH1t + col * 68 + lb) = st;
            }
        }
        __syncthreads();

        // GEMM2: z2[l, a] = H1 @ W2 ; fold relu + W3 into scores
        #pragma unroll
        for (int j = 0; j < 4; j++)
            #pragma unroll
            for (int k = 0; k < 4; k++) acc[j][k] = 0ULL;

        #pragma unroll 4
        for (int e = 0; e < AB; e++) {
            float4 h4 = *(const float4*)(sH1t + e * 68 + lb);
            ulonglong2 b0 = *(const ulonglong2*)(sW2 + e * AB + c0);
            ulonglong2 b1v = *(const ulonglong2*)(sW2 + e * AB + c1);
            unsigned long long a0 = packdup(h4.x), a1 = packdup(h4.y);
            unsigned long long a2 = packdup(h4.z), a3 = packdup(h4.w);
            fma2(acc[0][0], a0, b0.x); fma2(acc[0][1], a0, b0.y);
            fma2(acc[0][2], a0, b1v.x); fma2(acc[0][3], a0, b1v.y);
            fma2(acc[1][0], a1, b0.x); fma2(acc[1][1], a1, b0.y);
            fma2(acc[1][2], a1, b1v.x); fma2(acc[1][3], a1, b1v.y);
            fma2(acc[2][0], a2, b0.x); fma2(acc[2][1], a2, b0.y);
            fma2(acc[2][2], a2, b1v.x); fma2(acc[2][3], a2, b1v.y);
            fma2(acc[3][0], a3, b0.x); fma2(acc[3][1], a3, b0.y);
            fma2(acc[3][2], a3, b1v.x); fma2(acc[3][3], a3, b1v.y);
        }

        {
            float hv[4][8];
            #pragma unroll
            for (int j = 0; j < 4; j++) {
                unpack2(acc[j][0], hv[j][0], hv[j][1]);
                unpack2(acc[j][1], hv[j][2], hv[j][3]);
                unpack2(acc[j][2], hv[j][4], hv[j][5]);
                unpack2(acc[j][3], hv[j][6], hv[j][7]);
            }
            float sc[4] = {0.f, 0.f, 0.f, 0.f};
            #pragma unroll
            for (int k = 0; k < 8; k++) {
                int col = (k < 4) ? (c0 + k) : (c1 + k - 4);
                float bb = sB2[col], w3 = sW3[col];
                #pragma unroll
                for (int j = 0; j < 4; j++)
                    sc[j] += fmaxf(hv[j][k] + bb, 0.0f) * w3;
            }
            // the 16 threads sharing this lt are exactly one half-warp -> shuffle reduce
            #pragma unroll
            for (int off = 8; off > 0; off >>= 1) {
                #pragma unroll
                for (int j = 0; j < 4; j++)
                    sc[j] += __shfl_down_sync(0xffffffffu, sc[j], off, 16);
            }
            if ((t & 15) == 0) {
                #pragma unroll
                for (int j = 0; j < 4; j++)
                    sSc[l0 + lb + j] += sc[j];   // single writer per score
            }
        }
        __syncthreads();
    }

    // ---- tail: rows 192..199 (8 rows) ----
    {
        for (int idx = t; idx < 8 * EB; idx += 256) {
            int l = idx >> 7, e = idx & 127;
            sKt[e * 64 + l] = keys[((size_t)b * LK + 192 + l) * EB + e]
                            + pos_emb[(192 + l) * EB + e];
        }
        __syncthreads();

        int a = t & 127, lg = t >> 7;   // each thread: col a, rows lg*4..lg*4+3
        float z1[4] = {0.f, 0.f, 0.f, 0.f};
        #pragma unroll 4
        for (int e = 0; e < EB; e++) {
            float4 k4 = *(const float4*)(sKt + e * 64 + lg * 4);
            float w = sWb[e * AB + a];
            z1[0] += k4.x * w; z1[1] += k4.y * w;
            z1[2] += k4.z * w; z1[3] += k4.w * w;
        }
        float u = sU[a];
        float4 st;
        st.x = fmaxf(z1[0] + u, 0.0f);
        st.y = fmaxf(z1[1] + u, 0.0f);
        st.z = fmaxf(z1[2] + u, 0.0f);
        st.w = fmaxf(z1[3] + u, 0.0f);
        *(float4*)(sH1t + a * 68 + lg * 4) = st;
        __syncthreads();

        float z2[4] = {0.f, 0.f, 0.f, 0.f};
        #pragma unroll 4
        for (int e = 0; e < AB; e++) {
            float4 h4 = *(const float4*)(sH1t + e * 68 + lg * 4);
            float w = sW2[e * AB + a];
            z2[0] += h4.x * w; z2[1] += h4.y * w;
            z2[2] += h4.z * w; z2[3] += h4.w * w;
        }
        float bb = sB2[a], w3 = sW3[a];
        float p[4];
        #pragma unroll
        for (int j = 0; j < 4; j++) p[j] = fmaxf(z2[j] + bb, 0.0f) * w3;
        #pragma unroll
        for (int off = 16; off > 0; off >>= 1) {
            #pragma unroll
            for (int j = 0; j < 4; j++)
                p[j] += __shfl_down_sync(0xffffffffu, p[j], off);
        }
        if ((t & 31) == 0) {
            #pragma unroll
            for (int j = 0; j < 4; j++)
                atomicAdd(&sSc[192 + lg * 4 + j], p[j]);
        }
    }
    __syncthreads();

    // ---- softmax over valid l ----
    int kli;
    if (g_len64) kli = (int)((const long long*)keys_length)[b];
    else         kli = ((const int*)keys_length)[b];
    kli = min(max(kli, 0), LK);            // defensive clamp (no OOB ever)

    float m = -3.0e38f;
    if (t < kli) m = sSc[t];
    sRed[t] = m;
    __syncthreads();
    #pragma unroll
    for (int s = 128; s > 0; s >>= 1) {
        if (t < s) sRed[t] = fmaxf(sRed[t], sRed[t + s]);
        __syncthreads();
    }
    m = sRed[0];
    __syncthreads();

    float wgt = 0.0f;
    if (t < kli) { wgt = expf(sSc[t] - m); }
    if (t < LK) sSc[t] = wgt;   // zero weights for invalid entries
    sRed[t] = wgt;
    __syncthreads();
    #pragma unroll
    for (int s = 128; s > 0; s >>= 1) {
        if (t < s) sRed[t] += sRed[t + s];
        __syncthreads();
    }
    const float inv = 1.0f / sRed[0];
    __syncthreads();

    // ---- weighted sum of keys_p ----
    {
        int ei = t & 127, half = t >> 7;
        float acc = 0.0f;
        const float* kb = keys + (size_t)b * LK * EB;
        for (int l = half; l < kli; l += 2)
            acc += sSc[l] * (kb[l * EB + ei] + pos_emb[l * EB + ei]);
        sRed[t] = acc;
        __syncthreads();
        if (t < 128)
            out[(size_t)b * EB + t] = (sRed[t] + sRed[t + 128]) * inv;
    }
}

extern "C" void kernel_launch(void* const* d_in, const int* in_sizes, int n_in,
                              void* d_out, int out_size) {
    const float* query       = (const float*)d_in[0];
    const float* keys        = (const float*)d_in[1];
    const void*  keys_length = d_in[2];
    const float* pos_emb     = (const float*)d_in[3];
    const float* W1          = (const float*)d_in[4];
    const float* b1          = (const float*)d_in[5];
    const float* W2          = (const float*)d_in[6];
    const float* b2          = (const float*)d_in[7];
    const float* W3          = (const float*)d_in[8];
    const float* b3          = (const float*)d_in[9];
    float* out = (float*)d_out;

    const int B = in_sizes[2];  // 4096

    detect_len_kernel<<<1, 256>>>((const unsigned int*)keys_length, B);
    prep_kernel<<<64, 256>>>(W1);

    cudaFuncSetAttribute(din_kernel, cudaFuncAttributeMaxDynamicSharedMemorySize, SMEM_BYTES);
    din_kernel<<<4096, 256, SMEM_BYTES>>>(query, keys, keys_length, pos_emb,
                                          W1, b1, W2, b2, W3, b3, out);
}